// round 12
// baseline (speedup 1.0000x reference)
#include <cuda_runtime.h>
#include <cuda_bf16.h>
#include <cstdint>
#include <math.h>

// QuantumNet fused, round 11: loads via cp.async.bulk (TMA/UBLKCP path,
// 1D, no tensormap) + mbarrier completion, bypassing the per-lane
// L1tex wavefront queue blamed for the ~4TB/s cap of cp.async variants.
// Compute structure = R3 (thread-per-row, broadcast weight LDS, depth-2
// ring), epilogue = collapsed Clifford form.

#define KDIM 512
#define ROWS 64
#define THREADS 64
#define KTILE 64
#define NTILES (KDIM / KTILE)   // 8
#define NSTAGES 2
#define XS_STRIDE 68            // 64 + 4 pad: 272B rows, 16B-aligned
#define TILE_ROW_BYTES (KTILE * 4)          // 256
#define TILE_BYTES (ROWS * TILE_ROW_BYTES)  // 16384

__device__ __forceinline__ unsigned smem_u32(const void* p) {
    return (unsigned)__cvta_generic_to_shared(p);
}

__device__ __forceinline__ void mbar_init(unsigned mbar, unsigned count) {
    asm volatile("mbarrier.init.shared.b64 [%0], %1;" :: "r"(mbar), "r"(count) : "memory");
}

__device__ __forceinline__ void mbar_expect_tx(unsigned mbar, unsigned bytes) {
    asm volatile("mbarrier.arrive.expect_tx.shared.b64 _, [%0], %1;"
                 :: "r"(mbar), "r"(bytes) : "memory");
}

__device__ __forceinline__ void bulk_ld(unsigned dst_smem, const void* src,
                                        unsigned bytes, unsigned mbar) {
    asm volatile(
        "cp.async.bulk.shared::cluster.global.mbarrier::complete_tx::bytes "
        "[%0], [%1], %2, [%3];"
        :: "r"(dst_smem), "l"(src), "r"(bytes), "r"(mbar) : "memory");
}

__device__ __forceinline__ void mbar_wait(unsigned mbar, unsigned parity) {
    asm volatile(
        "{\n\t"
        ".reg .pred P1;\n\t"
        "WAIT_LOOP_%=:\n\t"
        "mbarrier.try_wait.parity.acquire.cta.shared::cta.b64 P1, [%0], %1, 0x989680;\n\t"
        "@P1 bra.uni WAIT_DONE_%=;\n\t"
        "bra.uni WAIT_LOOP_%=;\n\t"
        "WAIT_DONE_%=:\n\t"
        "}"
        :: "r"(mbar), "r"(parity) : "memory");
}

__global__ __launch_bounds__(THREADS)
void qnet_kernel(const float* __restrict__ x,
                 const float* __restrict__ pre_w,
                 const float* __restrict__ pre_b,
                 const float* __restrict__ u3p,
                 const float* __restrict__ post_w,
                 const float* __restrict__ post_b,
                 float* __restrict__ out, int B)
{
    __shared__ float wts[KDIM * 4];                    // 8 KB [k][q]
    __shared__ float xs[NSTAGES][ROWS * XS_STRIDE];    // 2 x 17.4 KB
    __shared__ __align__(8) unsigned long long mbar[NSTAGES];

    const int tid  = threadIdx.x;
    const int row0 = blockIdx.x * ROWS;
    const int row  = row0 + tid;
    const int nrows = (B - row0 < ROWS) ? (B - row0) : ROWS;

    #pragma unroll
    for (int i = tid; i < KDIM * 4; i += THREADS) {
        int q = i >> 9;
        int k = i & (KDIM - 1);
        wts[k * 4 + q] = pre_w[i];
    }

    unsigned mb[NSTAGES];
    #pragma unroll
    for (int s = 0; s < NSTAGES; ++s) mb[s] = smem_u32(&mbar[s]);
    unsigned xsa[NSTAGES];
    #pragma unroll
    for (int s = 0; s < NSTAGES; ++s) xsa[s] = smem_u32(&xs[s][0]);

    if (tid == 0) {
        mbar_init(mb[0], 1);
        mbar_init(mb[1], 1);
        asm volatile("fence.proxy.async.shared::cta;" ::: "memory");
    }
    __syncthreads();   // mbar init + wts visible

    // issue tile kt into stage s: 1 expect_tx + one 256B bulk copy per row
    auto issue_tile = [&](int kt, int s) {
        if (tid == 0)
            mbar_expect_tx(mb[s], (unsigned)(nrows * TILE_ROW_BYTES));
        if (tid < nrows)
            bulk_ld(xsa[s] + (unsigned)(tid * XS_STRIDE * 4),
                    x + (size_t)row * KDIM + kt * KTILE,
                    TILE_ROW_BYTES, mb[s]);
    };

    issue_tile(0, 0);
    issue_tile(1, 1);

    float acc0 = 0.f, acc1 = 0.f, acc2 = 0.f, acc3 = 0.f;

    #pragma unroll
    for (int kt = 0; kt < NTILES; ++kt) {
        const int s = kt & 1;
        mbar_wait(mb[s], (kt >> 1) & 1);

        const int kbase = kt * KTILE;
        #pragma unroll
        for (int k = 0; k < KTILE; k += 4) {
            float4 xv = *(const float4*)&xs[s][tid * XS_STRIDE + k];
            float4 w0 = *(const float4*)&wts[(kbase + k + 0) * 4];
            float4 w1 = *(const float4*)&wts[(kbase + k + 1) * 4];
            float4 w2 = *(const float4*)&wts[(kbase + k + 2) * 4];
            float4 w3 = *(const float4*)&wts[(kbase + k + 3) * 4];
            acc0 = fmaf(xv.x, w0.x, acc0); acc1 = fmaf(xv.x, w0.y, acc1);
            acc2 = fmaf(xv.x, w0.z, acc2); acc3 = fmaf(xv.x, w0.w, acc3);
            acc0 = fmaf(xv.y, w1.x, acc0); acc1 = fmaf(xv.y, w1.y, acc1);
            acc2 = fmaf(xv.y, w1.z, acc2); acc3 = fmaf(xv.y, w1.w, acc3);
            acc0 = fmaf(xv.z, w2.x, acc0); acc1 = fmaf(xv.z, w2.y, acc1);
            acc2 = fmaf(xv.z, w2.z, acc2); acc3 = fmaf(xv.z, w2.w, acc3);
            acc0 = fmaf(xv.w, w3.x, acc0); acc1 = fmaf(xv.w, w3.y, acc1);
            acc2 = fmaf(xv.w, w3.z, acc2); acc3 = fmaf(xv.w, w3.w, acc3);
        }
        __syncthreads();   // all threads done reading stage s

        if (kt + NSTAGES < NTILES)
            issue_tile(kt + NSTAGES, s);
    }

    if (row >= B) return;

    // ---- collapsed epilogue (Clifford-conjugated Pauli strings) ----
    const float HALF_PI = 1.5707963267948966f;
    float z[4], xq[4], yq[4];
    float pre[4] = { acc0 + pre_b[0], acc1 + pre_b[1],
                     acc2 + pre_b[2], acc3 + pre_b[3] };
    #pragma unroll
    for (int q = 0; q < 4; ++q) {
        float t  = tanhf(pre[q] * 0.1f) * HALF_PI;
        float u  = t * t;
        float cr = rsqrtf(fmaf(t, t, 1.f));
        float cz = rsqrtf(fmaf(u, u, 1.f));
        z[q]  = -t * cr;
        xq[q] = cr * cz;
        yq[q] = xq[q] * u;
    }

    float cg[4], mx[4], my[4];
    #pragma unroll
    for (int q = 0; q < 4; ++q) {
        float th = u3p[q * 3 + 0];
        float la = u3p[q * 3 + 2];
        float st_, ct_, sl_, cl_;
        __sincosf(th, &st_, &ct_);
        __sincosf(la, &sl_, &cl_);
        cg[q] = ct_;
        mx[q] = -st_ * cl_;
        my[q] =  st_ * sl_;
    }

    // Z~: Z0Z1Z2 | Z0Z1Z2Z3 | Z0Z3 | Z2Z3
    // X~: X0X1X2X3 | X0X2X3 | X0X1 | X1X2
    // Y~: -Y0Y1Y2X3 | -Y0Z1Y2Y3 | Y0X1Z3 | X1Y2Z3
    float z01 = z[0] * z[1];
    float E0 = cg[0] * (z01 * z[2])
             + mx[0] * (xq[0] * xq[1] * xq[2] * xq[3])
             - my[0] * (yq[0] * yq[1] * yq[2] * xq[3]);
    float E1 = cg[1] * (z01 * z[2] * z[3])
             + mx[1] * (xq[0] * xq[2] * xq[3])
             - my[1] * (yq[0] * z[1] * yq[2] * yq[3]);
    float E2 = cg[2] * (z[0] * z[3])
             + mx[2] * (xq[0] * xq[1])
             + my[2] * (yq[0] * xq[1] * z[3]);
    float E3 = cg[3] * (z[2] * z[3])
             + mx[3] * (xq[1] * xq[2])
             + my[3] * (xq[1] * yq[2] * z[3]);

    float o0 = post_b[0], o1 = post_b[1];
    o0 = fmaf(post_w[0], E0, o0); o1 = fmaf(post_w[4], E0, o1);
    o0 = fmaf(post_w[1], E1, o0); o1 = fmaf(post_w[5], E1, o1);
    o0 = fmaf(post_w[2], E2, o0); o1 = fmaf(post_w[6], E2, o1);
    o0 = fmaf(post_w[3], E3, o0); o1 = fmaf(post_w[7], E3, o1);

    float2 res; res.x = o0; res.y = o1;
    ((float2*)out)[row] = res;
}

extern "C" void kernel_launch(void* const* d_in, const int* in_sizes, int n_in,
                              void* d_out, int out_size) {
    const float* x      = (const float*)d_in[0];
    const float* pre_w  = (const float*)d_in[1];
    const float* pre_b  = (const float*)d_in[2];
    const float* u3p    = (const float*)d_in[3];
    const float* post_w = (const float*)d_in[4];
    const float* post_b = (const float*)d_in[5];
    float* out = (float*)d_out;

    int B = in_sizes[0] / KDIM;
    int grid = (B + ROWS - 1) / ROWS;
    qnet_kernel<<<grid, THREADS>>>(x, pre_w, pre_b, u3p, post_w, post_b, out, B);
}

// round 13
// speedup vs baseline: 1.2522x; 1.2522x over previous
#include <cuda_runtime.h>
#include <cuda_bf16.h>
#include <cstdint>
#include <math.h>

// QuantumNet fused, round 12: DRAM-page-friendly row-chunk streaming.
//  - chunk = 4 full rows (8KB contiguous) via one cp.async.bulk -> linear
//    DRAM bursts (row-buffer friendly), depth-3 mbarrier ring
//  - warp-per-row compute: lanes sweep K contiguously (conflict-free LDS),
//    weights in 64 registers per lane (no weight smem at all)
//  - butterfly reduce -> smem partials -> collapsed Clifford epilogue

#define KDIM 512
#define ROWS 32                 // rows per CTA
#define THREADS 128             // 4 warps
#define CHUNK_ROWS 4
#define NCHUNKS (ROWS / CHUNK_ROWS)    // 8
#define NSTAGES 3
#define CHUNK_FLOATS (CHUNK_ROWS * KDIM)   // 2048
#define CHUNK_BYTES (CHUNK_FLOATS * 4)     // 8192

__device__ __forceinline__ unsigned smem_u32(const void* p) {
    return (unsigned)__cvta_generic_to_shared(p);
}
__device__ __forceinline__ void mbar_init(unsigned mbar, unsigned count) {
    asm volatile("mbarrier.init.shared.b64 [%0], %1;" :: "r"(mbar), "r"(count) : "memory");
}
__device__ __forceinline__ void mbar_expect_tx(unsigned mbar, unsigned bytes) {
    asm volatile("mbarrier.arrive.expect_tx.shared.b64 _, [%0], %1;"
                 :: "r"(mbar), "r"(bytes) : "memory");
}
__device__ __forceinline__ void bulk_ld(unsigned dst_smem, const void* src,
                                        unsigned bytes, unsigned mbar) {
    asm volatile(
        "cp.async.bulk.shared::cluster.global.mbarrier::complete_tx::bytes "
        "[%0], [%1], %2, [%3];"
        :: "r"(dst_smem), "l"(src), "r"(bytes), "r"(mbar) : "memory");
}
__device__ __forceinline__ void mbar_wait(unsigned mbar, unsigned parity) {
    asm volatile(
        "{\n\t"
        ".reg .pred P1;\n\t"
        "WAIT_LOOP_%=:\n\t"
        "mbarrier.try_wait.parity.acquire.cta.shared::cta.b64 P1, [%0], %1, 0x989680;\n\t"
        "@P1 bra.uni WAIT_DONE_%=;\n\t"
        "bra.uni WAIT_LOOP_%=;\n\t"
        "WAIT_DONE_%=:\n\t"
        "}"
        :: "r"(mbar), "r"(parity) : "memory");
}

__global__ __launch_bounds__(THREADS)
void qnet_kernel(const float* __restrict__ x,
                 const float* __restrict__ pre_w,
                 const float* __restrict__ pre_b,
                 const float* __restrict__ u3p,
                 const float* __restrict__ post_w,
                 const float* __restrict__ post_b,
                 float* __restrict__ out, int B)
{
    __shared__ float xs[NSTAGES][CHUNK_FLOATS];          // 3 x 8 KB
    __shared__ float red[ROWS * 4];                      // 512 B partials
    __shared__ __align__(8) unsigned long long mbar[NSTAGES];

    const int tid  = threadIdx.x;
    const int wid  = tid >> 5;         // warp 0..3 -> row within chunk
    const int lane = tid & 31;
    const int row0 = blockIdx.x * ROWS;
    const int nrows = (B - row0 < ROWS) ? (B - row0) : ROWS;

    // ---- weights into registers: lane covers k = i*128 + lane*4 + m ----
    float wreg[4][4][4];   // [i][m][q]
    #pragma unroll
    for (int i = 0; i < 4; ++i)
        #pragma unroll
        for (int q = 0; q < 4; ++q) {
            float4 v = *(const float4*)(pre_w + q * KDIM + i * 128 + lane * 4);
            wreg[i][0][q] = v.x; wreg[i][1][q] = v.y;
            wreg[i][2][q] = v.z; wreg[i][3][q] = v.w;
        }

    unsigned mb[NSTAGES], xsa[NSTAGES];
    #pragma unroll
    for (int s = 0; s < NSTAGES; ++s) {
        mb[s]  = smem_u32(&mbar[s]);
        xsa[s] = smem_u32(&xs[s][0]);
    }

    if (tid == 0) {
        #pragma unroll
        for (int s = 0; s < NSTAGES; ++s) mbar_init(mb[s], 1);
        asm volatile("fence.proxy.async.shared::cta;" ::: "memory");
    }
    __syncthreads();

    // one 8KB linear bulk copy per chunk
    auto issue_chunk = [&](int c, int s) {
        if (tid == 0) {
            int cr = nrows - c * CHUNK_ROWS;
            if (cr > CHUNK_ROWS) cr = CHUNK_ROWS;
            unsigned bytes = (cr > 0) ? (unsigned)(cr * KDIM * 4) : 0u;
            mbar_expect_tx(mb[s], bytes);
            if (bytes)
                bulk_ld(xsa[s], x + ((size_t)row0 + c * CHUNK_ROWS) * KDIM,
                        bytes, mb[s]);
        }
    };

    issue_chunk(0, 0);
    issue_chunk(1, 1);
    issue_chunk(2, 2);

    #pragma unroll
    for (int c = 0; c < NCHUNKS; ++c) {
        const int s = c % NSTAGES;
        mbar_wait(mb[s], (c / NSTAGES) & 1);

        const int lrow = c * CHUNK_ROWS + wid;   // CTA-local row this warp owns
        if (lrow < nrows) {
            float a0 = 0.f, a1 = 0.f, a2 = 0.f, a3 = 0.f;
            const float4* xv4 = (const float4*)&xs[s][wid * KDIM];
            #pragma unroll
            for (int i = 0; i < 4; ++i) {
                float4 xv = xv4[i * 32 + lane];
                a0 = fmaf(xv.x, wreg[i][0][0], a0); a1 = fmaf(xv.x, wreg[i][0][1], a1);
                a2 = fmaf(xv.x, wreg[i][0][2], a2); a3 = fmaf(xv.x, wreg[i][0][3], a3);
                a0 = fmaf(xv.y, wreg[i][1][0], a0); a1 = fmaf(xv.y, wreg[i][1][1], a1);
                a2 = fmaf(xv.y, wreg[i][1][2], a2); a3 = fmaf(xv.y, wreg[i][1][3], a3);
                a0 = fmaf(xv.z, wreg[i][2][0], a0); a1 = fmaf(xv.z, wreg[i][2][1], a1);
                a2 = fmaf(xv.z, wreg[i][2][2], a2); a3 = fmaf(xv.z, wreg[i][2][3], a3);
                a0 = fmaf(xv.w, wreg[i][3][0], a0); a1 = fmaf(xv.w, wreg[i][3][1], a1);
                a2 = fmaf(xv.w, wreg[i][3][2], a2); a3 = fmaf(xv.w, wreg[i][3][3], a3);
            }
            // butterfly reduce the 4 accumulators over the warp
            #pragma unroll
            for (int off = 16; off >= 1; off >>= 1) {
                a0 += __shfl_xor_sync(0xFFFFFFFFu, a0, off);
                a1 += __shfl_xor_sync(0xFFFFFFFFu, a1, off);
                a2 += __shfl_xor_sync(0xFFFFFFFFu, a2, off);
                a3 += __shfl_xor_sync(0xFFFFFFFFu, a3, off);
            }
            if (lane == 0) {
                float4 v; v.x = a0; v.y = a1; v.z = a2; v.w = a3;
                *(float4*)&red[lrow * 4] = v;
            }
        }
        __syncthreads();   // all warps done with stage s (and red write ordered)

        if (c + NSTAGES < NCHUNKS)
            issue_chunk(c + NSTAGES, s);
    }

    // ---- epilogue: one thread per row ----
    if (tid >= nrows) return;
    float4 pv = *(const float4*)&red[tid * 4];
    const int row = row0 + tid;

    const float HALF_PI = 1.5707963267948966f;
    float z[4], xq[4], yq[4];
    float pre[4] = { pv.x + pre_b[0], pv.y + pre_b[1],
                     pv.z + pre_b[2], pv.w + pre_b[3] };
    #pragma unroll
    for (int q = 0; q < 4; ++q) {
        float t  = tanhf(pre[q] * 0.1f) * HALF_PI;
        float u  = t * t;
        float cr = rsqrtf(fmaf(t, t, 1.f));
        float cz = rsqrtf(fmaf(u, u, 1.f));
        z[q]  = -t * cr;
        xq[q] = cr * cz;
        yq[q] = xq[q] * u;
    }

    float cg[4], mx[4], my[4];
    #pragma unroll
    for (int q = 0; q < 4; ++q) {
        float th = u3p[q * 3 + 0];
        float la = u3p[q * 3 + 2];
        float st_, ct_, sl_, cl_;
        __sincosf(th, &st_, &ct_);
        __sincosf(la, &sl_, &cl_);
        cg[q] = ct_;
        mx[q] = -st_ * cl_;
        my[q] =  st_ * sl_;
    }

    // Clifford-conjugated Pauli strings:
    // Z~: Z0Z1Z2 | Z0Z1Z2Z3 | Z0Z3 | Z2Z3
    // X~: X0X1X2X3 | X0X2X3 | X0X1 | X1X2
    // Y~: -Y0Y1Y2X3 | -Y0Z1Y2Y3 | Y0X1Z3 | X1Y2Z3
    float z01 = z[0] * z[1];
    float E0 = cg[0] * (z01 * z[2])
             + mx[0] * (xq[0] * xq[1] * xq[2] * xq[3])
             - my[0] * (yq[0] * yq[1] * yq[2] * xq[3]);
    float E1 = cg[1] * (z01 * z[2] * z[3])
             + mx[1] * (xq[0] * xq[2] * xq[3])
             - my[1] * (yq[0] * z[1] * yq[2] * yq[3]);
    float E2 = cg[2] * (z[0] * z[3])
             + mx[2] * (xq[0] * xq[1])
             + my[2] * (yq[0] * xq[1] * z[3]);
    float E3 = cg[3] * (z[2] * z[3])
             + mx[3] * (xq[1] * xq[2])
             + my[3] * (xq[1] * yq[2] * z[3]);

    float o0 = post_b[0], o1 = post_b[1];
    o0 = fmaf(post_w[0], E0, o0); o1 = fmaf(post_w[4], E0, o1);
    o0 = fmaf(post_w[1], E1, o0); o1 = fmaf(post_w[5], E1, o1);
    o0 = fmaf(post_w[2], E2, o0); o1 = fmaf(post_w[6], E2, o1);
    o0 = fmaf(post_w[3], E3, o0); o1 = fmaf(post_w[7], E3, o1);

    float2 res; res.x = o0; res.y = o1;
    ((float2*)out)[row] = res;
}

extern "C" void kernel_launch(void* const* d_in, const int* in_sizes, int n_in,
                              void* d_out, int out_size) {
    const float* x      = (const float*)d_in[0];
    const float* pre_w  = (const float*)d_in[1];
    const float* pre_b  = (const float*)d_in[2];
    const float* u3p    = (const float*)d_in[3];
    const float* post_w = (const float*)d_in[4];
    const float* post_b = (const float*)d_in[5];
    float* out = (float*)d_out;

    int B = in_sizes[0] / KDIM;
    int grid = (B + ROWS - 1) / ROWS;
    qnet_kernel<<<grid, THREADS>>>(x, pre_w, pre_b, u3p, post_w, post_b, out, B);
}